// round 8
// baseline (speedup 1.0000x reference)
#include <cuda_runtime.h>
#include <cuda_bf16.h>

#define NSP 262144   // 64^3
typedef unsigned long long u64;

// ---------------- scratch ---------------------------------------------------
__device__ float g_q[8 * NSP];      // layout0 (c,h,w,d)
__device__ float g_k[8 * NSP];
__device__ float g_v[64 * NSP];
__device__ float g_qT1[8 * NSP];    // layout1 (c,h,d,w)
__device__ float g_kT1[8 * NSP];
__device__ float g_vT1[64 * NSP];
__device__ float g_qT2[8 * NSP];    // layout2 (c,w,d,h)
__device__ float g_kT2[8 * NSP];
__device__ float g_vT2[64 * NSP];
__device__ float g_p1[64 * NSP];
__device__ float g_p2[64 * NSP];
__device__ float g_m[3 * NSP];
__device__ float g_s[3 * NSP];

// ---------------- helpers ----------------------------------------------------
__device__ __forceinline__ u64 pack2(float a, float b) {
    u64 r; asm("mov.b64 %0,{%1,%2};" : "=l"(r) : "f"(a), "f"(b)); return r;
}
__device__ __forceinline__ void fma2(u64& d, u64 a, u64 b) {
    asm("fma.rn.f32x2 %0,%1,%2,%0;" : "+l"(d) : "l"(a), "l"(b));
}
__device__ __forceinline__ unsigned smem_u32(const void* p) {
    unsigned a;
    asm("{.reg .u64 t; cvta.to.shared.u64 t, %1; cvt.u32.u64 %0, t;}" : "=r"(a) : "l"(p));
    return a;
}
__device__ __forceinline__ void ldsm_x4(unsigned& a0, unsigned& a1, unsigned& a2, unsigned& a3, unsigned addr) {
    asm volatile("ldmatrix.sync.aligned.m8n8.x4.shared.b16 {%0,%1,%2,%3}, [%4];"
                 : "=r"(a0), "=r"(a1), "=r"(a2), "=r"(a3) : "r"(addr));
}
__device__ __forceinline__ void ldsm_x2_t(unsigned& b0, unsigned& b1, unsigned addr) {
    asm volatile("ldmatrix.sync.aligned.m8n8.x2.trans.shared.b16 {%0,%1}, [%2];"
                 : "=r"(b0), "=r"(b1) : "r"(addr));
}
__device__ __forceinline__ void mma_bf16(float* d, unsigned a0, unsigned a1, unsigned a2, unsigned a3,
                                         unsigned b0, unsigned b1) {
    asm volatile("mma.sync.aligned.m16n8k16.row.col.f32.bf16.bf16.f32 "
                 "{%0,%1,%2,%3}, {%4,%5,%6,%7}, {%8,%9}, {%0,%1,%2,%3};"
                 : "+f"(d[0]), "+f"(d[1]), "+f"(d[2]), "+f"(d[3])
                 : "r"(a0), "r"(a1), "r"(a2), "r"(a3), "r"(b0), "r"(b1));
}

// original voxel index for (axis, line, position-in-line)
__device__ __forceinline__ int orig_idx(int axis, int l, int p) {
    if (axis == 0) return (l << 6) + p;
    if (axis == 1) return ((l >> 6) << 12) + (p << 6) + (l & 63);
    return (p << 12) + ((l >> 6) << 6) + (l & 63);
}

// ---------------- projection (coalesced, FFMA2) ------------------------------
__global__ __launch_bounds__(256) void proj_kernel(
    const float* __restrict__ x,
    const float* __restrict__ tw, const float* __restrict__ tb,
    const float* __restrict__ pw, const float* __restrict__ pb,
    const float* __restrict__ gw, const float* __restrict__ gb)
{
    __shared__ u64 ws2[80 * 64];
    __shared__ float sb[80];
    const int tid = threadIdx.x;

    for (int j = tid; j < 80 * 64; j += 256) {
        int o = j >> 6, c = j & 63;
        float w;
        if (o < 8)       w = tw[o * 64 + c];
        else if (o < 16) w = pw[(o - 8) * 64 + c];
        else             w = gw[(o - 16) * 64 + c];
        ws2[j] = pack2(w, w);
    }
    if (tid < 80) sb[tid] = (tid < 8) ? tb[tid] : (tid < 16) ? pb[tid - 8] : gb[tid - 16];
    __syncthreads();

    const int v4 = blockIdx.x * 256 + tid;
    const ulonglong2* x2 = reinterpret_cast<const ulonglong2*>(x);

    #pragma unroll 1
    for (int t = 0; t < 4; ++t) {
        u64 acc[20][2];
        #pragma unroll
        for (int j = 0; j < 20; ++j) {
            u64 b = pack2(sb[t * 20 + j], sb[t * 20 + j]);
            acc[j][0] = b; acc[j][1] = b;
        }
        #pragma unroll 4
        for (int c = 0; c < 64; ++c) {
            ulonglong2 xv = x2[c * (NSP / 4) + v4];
            #pragma unroll
            for (int j = 0; j < 20; ++j) {
                u64 w2 = ws2[(t * 20 + j) * 64 + c];
                fma2(acc[j][0], w2, xv.x);
                fma2(acc[j][1], w2, xv.y);
            }
        }
        #pragma unroll
        for (int j = 0; j < 20; ++j) {
            int o = t * 20 + j;
            float* dst = (o < 8)  ? (g_q + (size_t)o * NSP)
                       : (o < 16) ? (g_k + (size_t)(o - 8) * NSP)
                                  : (g_v + (size_t)(o - 16) * NSP);
            ulonglong2 st; st.x = acc[j][0]; st.y = acc[j][1];
            reinterpret_cast<ulonglong2*>(dst)[v4] = st;
        }
    }
}

// ---------------- transposes -------------------------------------------------
__global__ __launch_bounds__(256) void transpose_kernel(int which)
{
    __shared__ float sm[64][65];
    const int tid = threadIdx.x;
    const int bx = blockIdx.x, ch = blockIdx.y;

    const float* s; float* d;
    if (ch < 8)       { s = g_q + (size_t)ch * NSP;        d = (which == 1 ? g_qT1 : g_qT2) + (size_t)ch * NSP; }
    else if (ch < 16) { s = g_k + (size_t)(ch - 8) * NSP;  d = (which == 1 ? g_kT1 : g_kT2) + (size_t)(ch - 8) * NSP; }
    else              { s = g_v + (size_t)(ch - 16) * NSP; d = (which == 1 ? g_vT1 : g_vT2) + (size_t)(ch - 16) * NSP; }

    const int splane = (which == 1) ? bx * 4096 : bx * 64;
    const int srcRS  = (which == 1) ? 64 : 4096;
    const int dplane = bx * 4096;

    const int col = tid & 63, r0 = tid >> 6;
    #pragma unroll
    for (int it = 0; it < 16; ++it) {
        int r = r0 + it * 4;
        sm[r][col] = s[splane + r * srcRS + col];
    }
    __syncthreads();
    #pragma unroll
    for (int it = 0; it < 16; ++it) {
        int r = r0 + it * 4;
        d[dplane + r * 64 + col] = sm[col][r];
    }
}

// ---------------- per-axis softmax stats -------------------------------------
// Two-pass recompute: no e[64] array -> low registers, high occupancy.
__global__ __launch_bounds__(256) void stats_kernel(
    int axis, const float* __restrict__ qA, const float* __restrict__ kA)
{
    __shared__ float ksm[4][64][12];
    const int tid = threadIdx.x;
    const int ll = tid >> 6, p = tid & 63;
    const int l0 = blockIdx.x * 4;

    #pragma unroll
    for (int it = 0; it < 8; ++it) {
        int j = it * 256 + tid;
        int l2 = j >> 9, c = (j >> 6) & 7, g = j & 63;
        ksm[l2][g][c] = kA[c * NSP + (l0 + l2) * 64 + g];
    }
    float qr[8];
    #pragma unroll
    for (int c = 0; c < 8; ++c) qr[c] = qA[c * NSP + (l0 + ll) * 64 + p];
    __syncthreads();

    const bool diag = (axis == 2);
    const float4* kr = reinterpret_cast<const float4*>(&ksm[ll][0][0]);

    float m = -1e30f;
    #pragma unroll 4
    for (int g = 0; g < 64; ++g) {
        float4 k0 = kr[g * 3], k1 = kr[g * 3 + 1];
        float v = k0.x * qr[0] + k0.y * qr[1] + k0.z * qr[2] + k0.w * qr[3]
                + k1.x * qr[4] + k1.y * qr[5] + k1.z * qr[6] + k1.w * qr[7];
        if (diag && g == p) v = -1e30f;
        m = fmaxf(m, v);
    }
    float s = 0.f;
    #pragma unroll 4
    for (int g = 0; g < 64; ++g) {
        float4 k0 = kr[g * 3], k1 = kr[g * 3 + 1];
        float v = k0.x * qr[0] + k0.y * qr[1] + k0.z * qr[2] + k0.w * qr[3]
                + k1.x * qr[4] + k1.y * qr[5] + k1.z * qr[6] + k1.w * qr[7];
        if (diag && g == p) v = -1e30f;
        s += __expf(v - m);
    }

    int vx = orig_idx(axis, l0 + ll, p);
    g_m[axis * NSP + vx] = m;
    g_s[axis * NSP + vx] = s;
}

// ---------------- aggregation: E/softmax fp32 + bf16 tensor-core GEMM --------
// CTA = 1 line, 128 threads = 4 warps.
// O[c,p] = sum_g A[g,p] * V[g,c]  via  mma(m16n8k16): Amat = V^T [c][g] (row-major),
// Bmat = As [g][p] (k-row-major, loaded with ldmatrix.trans).
__global__ __launch_bounds__(128, 5) void agg_kernel(
    int axis, const float* __restrict__ qA, const float* __restrict__ kA,
    const float* __restrict__ vA, const float* __restrict__ src,
    float* __restrict__ dst, const float* __restrict__ gamma_ptr)
{
    __shared__ float qsm[8][64];
    __shared__ float ksm[64][12];                 // [g][c]
    __shared__ __nv_bfloat16 Vb[64][72];          // [c][g]  (A operand)
    __shared__ __nv_bfloat16 Ab[64][72];          // [g][p]  (B operand)
    __shared__ float Osm[64][68];                 // [c][p]
    __shared__ float sm_m[64], sm_r[64];

    const int tid = threadIdx.x;
    const int l = blockIdx.x;
    const int base = l * 64;

    #pragma unroll
    for (int it = 0; it < 4; ++it) {
        int j = it * 128 + tid;
        int c = j >> 6, g = j & 63;
        qsm[c][g] = qA[c * NSP + base + g];
        ksm[g][c] = kA[c * NSP + base + g];
    }
    #pragma unroll 8
    for (int it = 0; it < 32; ++it) {
        int j = it * 128 + tid;
        int c = j >> 6, g = j & 63;
        Vb[c][g] = __float2bfloat16(vA[c * NSP + base + g]);
    }
    if (tid < 64) {
        int vx = orig_idx(axis, l, tid);
        float m0 = g_m[vx], m1 = g_m[NSP + vx], m2 = g_m[2 * NSP + vx];
        float s0 = g_s[vx], s1 = g_s[NSP + vx], s2 = g_s[2 * NSP + vx];
        float m = fmaxf(m0, fmaxf(m1, m2));
        float st = s0 * __expf(m0 - m) + s1 * __expf(m1 - m) + s2 * __expf(m2 - m);
        sm_m[tid] = m;
        sm_r[tid] = gamma_ptr[0] / st;
    }
    __syncthreads();

    // ---- energies -> bf16 attention weights (gamma / softmax folded in) ----
    {
        const int gt = tid >> 4, pt = tid & 15;
        const int g0 = gt * 8, p0 = pt * 4;
        const float4 mv = *reinterpret_cast<const float4*>(&sm_m[p0]);
        const float4 rv = *reinterpret_cast<const float4*>(&sm_r[p0]);
        const float4* kr = reinterpret_cast<const float4*>(&ksm[0][0]);
        #pragma unroll
        for (int i = 0; i < 8; ++i) {
            int g = g0 + i;
            float4 k0 = kr[g * 3], k1 = kr[g * 3 + 1];
            float e0 = 0.f, e1 = 0.f, e2 = 0.f, e3 = 0.f;
            #pragma unroll
            for (int c = 0; c < 8; ++c) {
                float kc = (c < 4) ? ((c == 0) ? k0.x : (c == 1) ? k0.y : (c == 2) ? k0.z : k0.w)
                                   : ((c == 4) ? k1.x : (c == 5) ? k1.y : (c == 6) ? k1.z : k1.w);
                const float4 q4 = *reinterpret_cast<const float4*>(&qsm[c][p0]);
                e0 = fmaf(kc, q4.x, e0); e1 = fmaf(kc, q4.y, e1);
                e2 = fmaf(kc, q4.z, e2); e3 = fmaf(kc, q4.w, e3);
            }
            if (axis == 2) {
                if (g == p0)     e0 = -1e30f;
                if (g == p0 + 1) e1 = -1e30f;
                if (g == p0 + 2) e2 = -1e30f;
                if (g == p0 + 3) e3 = -1e30f;
            }
            float a0 = __expf(e0 - mv.x) * rv.x;
            float a1 = __expf(e1 - mv.y) * rv.y;
            float a2 = __expf(e2 - mv.z) * rv.z;
            float a3 = __expf(e3 - mv.w) * rv.w;
            __nv_bfloat162 w01; w01.x = __float2bfloat16(a0); w01.y = __float2bfloat16(a1);
            __nv_bfloat162 w23; w23.x = __float2bfloat16(a2); w23.y = __float2bfloat16(a3);
            *reinterpret_cast<__nv_bfloat162*>(&Ab[g][p0])     = w01;
            *reinterpret_cast<__nv_bfloat162*>(&Ab[g][p0 + 2]) = w23;
        }
    }
    __syncthreads();

    // ---- tensor-core GEMM: warp w owns c rows [16w, 16w+16) ----
    const int warp = tid >> 5, lane = tid & 31;
    const int c0 = warp * 16;

    float d[8][4];
    #pragma unroll
    for (int nt = 0; nt < 8; ++nt)
        #pragma unroll
        for (int j = 0; j < 4; ++j) d[nt][j] = 0.f;

    const unsigned a_base = smem_u32(&Vb[c0 + (lane & 15)][(lane >> 4) * 8]);
    #pragma unroll
    for (int kk = 0; kk < 4; ++kk) {
        unsigned a0, a1, a2, a3;
        ldsm_x4(a0, a1, a2, a3, a_base + kk * 32);     // +16 bf16 columns
        const unsigned b_row = smem_u32(&Ab[kk * 16 + (lane & 15)][0]);
        #pragma unroll
        for (int nt = 0; nt < 8; ++nt) {
            unsigned b0, b1;
            ldsm_x2_t(b0, b1, b_row + nt * 16);        // +8 bf16 columns
            mma_bf16(d[nt], a0, a1, a2, a3, b0, b1);
        }
    }

    // ---- D fragments -> Osm ----
    {
        const int r = lane >> 2, qc = (lane & 3) * 2;
        #pragma unroll
        for (int nt = 0; nt < 8; ++nt) {
            *reinterpret_cast<float2*>(&Osm[c0 + r][nt * 8 + qc])     = make_float2(d[nt][0], d[nt][1]);
            *reinterpret_cast<float2*>(&Osm[c0 + r + 8][nt * 8 + qc]) = make_float2(d[nt][2], d[nt][3]);
        }
    }
    __syncthreads();

    // ---- coalesced epilogue ----
    const int p = tid & 63;
    const bool addsrc = (axis == 0);
    #pragma unroll 8
    for (int c = tid >> 6; c < 64; c += 2) {
        size_t o = (size_t)c * NSP + base + p;
        float r = Osm[c][p];
        if (addsrc) r += src[o];
        dst[o] = r;
    }
}

// ---------------- transpose-add merge ---------------------------------------
__global__ __launch_bounds__(256) void merge_kernel(
    const float* __restrict__ P, float* __restrict__ out, int obaseMul, int ors)
{
    __shared__ float sm[64][65];
    const int tid = threadIdx.x;
    const int bx = blockIdx.x, c = blockIdx.y;
    const size_t pbase = (size_t)c * NSP + bx * 4096;
    const size_t obase = (size_t)c * NSP + (size_t)bx * obaseMul;

    const int col = tid & 63, r0 = tid >> 6;
    #pragma unroll
    for (int it = 0; it < 16; ++it) {
        int r = r0 + it * 4;
        sm[r][col] = P[pbase + r * 64 + col];
    }
    __syncthreads();
    #pragma unroll
    for (int it = 0; it < 16; ++it) {
        int r = r0 + it * 4;
        size_t o = obase + (size_t)r * ors + col;
        out[o] += sm[col][r];
    }
}

// ---------------- launch -----------------------------------------------------
extern "C" void kernel_launch(void* const* d_in, const int* in_sizes, int n_in,
                              void* d_out, int out_size)
{
    const float* x  = (const float*)d_in[0];
    const float* tw = (const float*)d_in[1];
    const float* tb = (const float*)d_in[2];
    const float* pw = (const float*)d_in[3];
    const float* pb = (const float*)d_in[4];
    const float* gw = (const float*)d_in[5];
    const float* gb = (const float*)d_in[6];
    const float* ga = (const float*)d_in[7];
    float* out = (float*)d_out;

    float *q, *k, *v, *qT1, *kT1, *vT1, *qT2, *kT2, *vT2, *p1, *p2;
    cudaGetSymbolAddress((void**)&q,   g_q);
    cudaGetSymbolAddress((void**)&k,   g_k);
    cudaGetSymbolAddress((void**)&v,   g_v);
    cudaGetSymbolAddress((void**)&qT1, g_qT1);
    cudaGetSymbolAddress((void**)&kT1, g_kT1);
    cudaGetSymbolAddress((void**)&vT1, g_vT1);
    cudaGetSymbolAddress((void**)&qT2, g_qT2);
    cudaGetSymbolAddress((void**)&kT2, g_kT2);
    cudaGetSymbolAddress((void**)&vT2, g_vT2);
    cudaGetSymbolAddress((void**)&p1,  g_p1);
    cudaGetSymbolAddress((void**)&p2,  g_p2);

    proj_kernel<<<256, 256>>>(x, tw, tb, pw, pb, gw, gb);
    transpose_kernel<<<dim3(64, 80), 256>>>(1);
    transpose_kernel<<<dim3(64, 80), 256>>>(2);
    stats_kernel<<<1024, 256>>>(0, q,   k);
    stats_kernel<<<1024, 256>>>(1, qT1, kT1);
    stats_kernel<<<1024, 256>>>(2, qT2, kT2);
    agg_kernel<<<4096, 128>>>(0, q,   k,   v,   x,       out, ga);
    agg_kernel<<<4096, 128>>>(1, qT1, kT1, vT1, nullptr, p1,  ga);
    agg_kernel<<<4096, 128>>>(2, qT2, kT2, vT2, nullptr, p2,  ga);
    merge_kernel<<<dim3(64, 64), 256>>>(p1, out, 4096, 64);
    merge_kernel<<<dim3(64, 64), 256>>>(p2, out, 64, 4096);
}